// round 14
// baseline (speedup 1.0000x reference)
#include <cuda_runtime.h>
#include <cstdint>

#define B 2
#define N 2048
#define C 768
#define CG 192                     // C/4 float4 groups
#define G 256                      // 2 CTAs/SM, all co-resident
#define T 256
#define ROWS_PER 16                // X rows per CTA chunk
#define XCHUNK_BYTES (ROWS_PER * C * 4)          // 49152
#define SH_OFF XCHUNK_BYTES
#define SMEM_BYTES (XCHUNK_BYTES + 2 * CG * 16)  // 55296

// Epoch double-buffered accumulators (zero-init; launch e uses [e&1], zeros [~e&1])
__device__ float g_s2[2][B][C];
__device__ float g_v2[2][B][C];

struct __align__(128) Cnt { unsigned v; unsigned pad[31]; };
__device__ Cnt g_bar4[2];          // monotonic arrival counters

__device__ __forceinline__ float4 f4add(float4 a, float4 b) {
    return make_float4(a.x + b.x, a.y + b.y, a.z + b.z, a.w + b.w);
}
__device__ __forceinline__ uint32_t smem_u32(const void* p) {
    uint32_t a;
    asm("{ .reg .u64 t; cvta.to.shared.u64 t, %1; cvt.u32.u64 %0, t; }"
        : "=r"(a) : "l"(p));
    return a;
}
__device__ __forceinline__ void mbar_wait(uint32_t mbar, uint32_t parity) {
    asm volatile(
        "{\n\t.reg .pred P;\n"
        "W_%=:\n\t"
        "mbarrier.try_wait.parity.shared.b64 P, [%0], %1;\n\t"
        "@!P bra W_%=;\n\t}"
        :: "r"(mbar), "r"(parity) : "memory");
}

// Fence-free grid barrier (R13 pattern): thread0 release-atomic arrival +
// acquire-load poll; bar.sync composes CTA-wide. Monotonic => replay-safe.
__device__ __forceinline__ void grid_barrier(int i) {
    __syncthreads();
    if (threadIdx.x == 0) {
        unsigned old;
        asm volatile("atom.release.gpu.global.add.u32 %0, [%1], %2;"
                     : "=r"(old) : "l"(&g_bar4[i].v), "r"(1u) : "memory");
        unsigned target = (old / G + 1u) * G;
        unsigned cur;
        do {
            asm volatile("ld.acquire.gpu.global.u32 %0, [%1];"
                         : "=r"(cur) : "l"(&g_bar4[i].v) : "memory");
        } while (cur < target);
    }
    __syncthreads();
}

extern __shared__ char smem_raw[];

__global__ void __launch_bounds__(T, 2)
fused_att_scores(const float4* __restrict__ X4, const float4* __restrict__ W4,
                 float* __restrict__ out) {
    float4* xbuf = (float4*)smem_raw;                 // 48 KB: this CTA's X rows
    float4* sh   = (float4*)(smem_raw + SH_OFF);      // 6 KB staging
    __shared__ uint64_t mbar_st;
    __shared__ float u0s[3], u1s[3];
    __shared__ int epoch_sh;
    const uint32_t mbar = smem_u32(&mbar_st);
    const int ct  = blockIdx.x;
    const int tid = threadIdx.x;
    const int wid = tid >> 5, lane = tid & 31;

    const int b = ct & 1, chunk = ct >> 1;            // 128 chunks per batch
    const int j0 = ct * 3;                            // this CTA's 3 j-rows
    const char* xsrc = (const char*)(X4 + ((size_t)b * N + chunk * ROWS_PER) * CG);

    // ---- Phase A: epoch read, TMA X, W prefetch, colsum -> REDG into s. ----
    if (tid == 0) {
        // Epoch: counter < (k+1)*G until ALL arrive; we haven't arrived yet,
        // so floor(val/G) = completed-launch count k. Stable across the CTA.
        unsigned v0 = *(volatile unsigned*)&g_bar4[0].v;
        epoch_sh = (int)((v0 / G) & 1u);
        asm volatile("mbarrier.init.shared.b64 [%0], 1;" :: "r"(mbar) : "memory");
        asm volatile("fence.proxy.async.shared::cta;" ::: "memory");
        asm volatile("mbarrier.arrive.expect_tx.shared.b64 _, [%0], %1;"
                     :: "r"(mbar), "r"((uint32_t)XCHUNK_BYTES) : "memory");
        asm volatile(
            "cp.async.bulk.shared::cta.global.mbarrier::complete_tx::bytes "
            "[%0], [%1], %2, [%3];"
            :: "r"(smem_u32(xbuf)), "l"(xsrc), "r"((uint32_t)XCHUNK_BYTES),
               "r"(mbar) : "memory");
    }
    // Prefetch this CTA's 6 W rows (3 Wq + 3 Wk = 144 lines of 128B) into L2.
    if (tid < 144) {
        const char* wq = (const char*)(W4 + (size_t)j0 * CG);
        const char* wk = (const char*)(W4 + (size_t)(C + j0) * CG);
        const char* p = (tid < 72) ? wq + tid * 128 : wk + (tid - 72) * 128;
        asm volatile("prefetch.global.L2 [%0];" :: "l"(p));
    }
    __syncthreads();
    const int e = epoch_sh;

    // Zero NEXT launch's buffers (nothing reads them this launch).
    if (tid < 6) {
        ((float*)g_s2[1 - e])[ct * 6 + tid] = 0.f;
        ((float*)g_v2[1 - e])[ct * 6 + tid] = 0.f;
    }

    mbar_wait(mbar, 0);
    if (tid < CG) {
        float4 a0 = make_float4(0.f, 0.f, 0.f, 0.f), a1 = a0;
#pragma unroll
        for (int r = 0; r < ROWS_PER; r += 2) {
            a0 = f4add(a0, xbuf[r * CG + tid]);
            a1 = f4add(a1, xbuf[(r + 1) * CG + tid]);
        }
        float4 s = f4add(a0, a1);
        float* dst = &g_s2[e][b][tid * 4];
        atomicAdd(dst + 0, s.x);
        atomicAdd(dst + 1, s.y);
        atomicAdd(dst + 2, s.z);
        atomicAdd(dst + 3, s.w);
    }
    grid_barrier(0);

    // ---- Phase B: u_j = Wk_j . s; REDG u_j * Wq_j into v. ----
    {
        for (int i = tid; i < 2 * CG; i += T)         // stage s (both batches)
            sh[i] = (i < CG) ? ((const float4*)g_s2[e][0])[i]
                             : ((const float4*)g_s2[e][1])[i - CG];
        __syncthreads();
        if (wid < 3) {
            const float4* row = W4 + (size_t)(C + j0 + wid) * CG;   // Wk (L2)
            float a0 = 0.f, a1 = 0.f;
#pragma unroll
            for (int k = 0; k < 6; ++k) {
                int c4 = lane + k * 32;
                float4 w  = row[c4];
                float4 v0 = sh[c4];
                float4 v1 = sh[CG + c4];
                a0 += w.x * v0.x + w.y * v0.y + w.z * v0.z + w.w * v0.w;
                a1 += w.x * v1.x + w.y * v1.y + w.z * v1.z + w.w * v1.w;
            }
#pragma unroll
            for (int o = 16; o > 0; o >>= 1) {
                a0 += __shfl_down_sync(0xFFFFFFFFu, a0, o);
                a1 += __shfl_down_sync(0xFFFFFFFFu, a1, o);
            }
            if (lane == 0) { u0s[wid] = a0; u1s[wid] = a1; }
        }
        __syncthreads();
        if (tid < CG) {
            float4 w0 = W4[(size_t)j0 * CG + tid];            // Wq rows (L2)
            float4 w1 = W4[(size_t)(j0 + 1) * CG + tid];
            float4 w2 = W4[(size_t)(j0 + 2) * CG + tid];
            float4 a0 = make_float4(
                w0.x * u0s[0] + w1.x * u0s[1] + w2.x * u0s[2],
                w0.y * u0s[0] + w1.y * u0s[1] + w2.y * u0s[2],
                w0.z * u0s[0] + w1.z * u0s[1] + w2.z * u0s[2],
                w0.w * u0s[0] + w1.w * u0s[1] + w2.w * u0s[2]);
            float4 a1 = make_float4(
                w0.x * u1s[0] + w1.x * u1s[1] + w2.x * u1s[2],
                w0.y * u1s[0] + w1.y * u1s[1] + w2.y * u1s[2],
                w0.z * u1s[0] + w1.z * u1s[1] + w2.z * u1s[2],
                w0.w * u1s[0] + w1.w * u1s[1] + w2.w * u1s[2]);
            float* d0 = &g_v2[e][0][tid * 4];
            float* d1 = &g_v2[e][1][tid * 4];
            atomicAdd(d0 + 0, a0.x); atomicAdd(d0 + 1, a0.y);
            atomicAdd(d0 + 2, a0.z); atomicAdd(d0 + 3, a0.w);
            atomicAdd(d1 + 0, a1.x); atomicAdd(d1 + 1, a1.y);
            atomicAdd(d1 + 2, a1.z); atomicAdd(d1 + 3, a1.w);
        }
    }
    grid_barrier(1);

    // ---- Phase C: scores from the X rows still in smem. ----
    {
        if (tid < CG) sh[tid] = ((const float4*)g_v2[e][b])[tid];
        __syncthreads();
        int nbase = chunk * ROWS_PER + wid * 2;
        float a[2];
#pragma unroll
        for (int r = 0; r < 2; ++r) {
            const float4* x = xbuf + (wid * 2 + r) * CG;
            float acc = 0.f;
#pragma unroll
            for (int k = 0; k < 6; ++k) {
                int c4 = lane + k * 32;
                float4 xv = x[c4];
                float4 vv = sh[c4];
                acc += xv.x * vv.x + xv.y * vv.y + xv.z * vv.z + xv.w * vv.w;
            }
            a[r] = acc;
        }
#pragma unroll
        for (int o = 16; o > 0; o >>= 1) {
#pragma unroll
            for (int r = 0; r < 2; ++r)
                a[r] += __shfl_down_sync(0xFFFFFFFFu, a[r], o);
        }
        if (lane == 0) {
#pragma unroll
            for (int r = 0; r < 2; ++r)
                out[b * N + nbase + r] = 0.125f * a[r];
        }
    }
}

extern "C" void kernel_launch(void* const* d_in, const int* in_sizes, int n_in,
                              void* d_out, int out_size) {
    const float4* X4 = (const float4*)d_in[0];  // [2, 2048, 768] f32
    const float4* W4 = (const float4*)d_in[1];  // [1536, 768] f32
    float* out = (float*)d_out;                 // [2, 2048] f32
    (void)in_sizes; (void)n_in; (void)out_size;

    cudaFuncSetAttribute(fused_att_scores,
                         cudaFuncAttributeMaxDynamicSharedMemorySize, SMEM_BYTES);
    fused_att_scores<<<G, T, SMEM_BYTES>>>(X4, W4, out);
}

// round 15
// speedup vs baseline: 1.5852x; 1.5852x over previous
#include <cuda_runtime.h>
#include <cstdint>

#define B 2
#define N 2048
#define C 768
#define CG 192                     // C/4 float4 groups
#define G 256                      // 2 CTAs/SM, all co-resident
#define T 256
#define ROWS_PER 16                // X rows per CTA chunk
#define XCHUNK_BYTES (ROWS_PER * C * 4)          // 49152
#define SH_OFF XCHUNK_BYTES
#define SMEM_BYTES (XCHUNK_BYTES + 2 * CG * 16)  // 55296
#define SCOPIES 4                  // staged copies for s (32 contenders/addr)
#define VCOPIES 8                  // staged copies for v (32 contenders/addr)

// Epoch double-buffered staged accumulators (zero-init symbols).
__device__ float g_s4[2][SCOPIES][B][C];   // 49 KB
__device__ float g_v4[2][VCOPIES][B][C];   // 98 KB

struct __align__(128) Cnt { unsigned v; unsigned pad[31]; };
__device__ Cnt g_bar4[2];          // monotonic arrival counters

__device__ __forceinline__ float4 f4add(float4 a, float4 b) {
    return make_float4(a.x + b.x, a.y + b.y, a.z + b.z, a.w + b.w);
}
__device__ __forceinline__ uint32_t smem_u32(const void* p) {
    uint32_t a;
    asm("{ .reg .u64 t; cvta.to.shared.u64 t, %1; cvt.u32.u64 %0, t; }"
        : "=r"(a) : "l"(p));
    return a;
}
__device__ __forceinline__ void mbar_wait(uint32_t mbar, uint32_t parity) {
    asm volatile(
        "{\n\t.reg .pred P;\n"
        "W_%=:\n\t"
        "mbarrier.try_wait.parity.shared.b64 P, [%0], %1;\n\t"
        "@!P bra W_%=;\n\t}"
        :: "r"(mbar), "r"(parity) : "memory");
}

// Fence-free grid barrier (R13 pattern). Monotonic => replay-safe.
__device__ __forceinline__ void grid_barrier(int i) {
    __syncthreads();
    if (threadIdx.x == 0) {
        unsigned old;
        asm volatile("atom.release.gpu.global.add.u32 %0, [%1], %2;"
                     : "=r"(old) : "l"(&g_bar4[i].v), "r"(1u) : "memory");
        unsigned target = (old / G + 1u) * G;
        unsigned cur;
        do {
            asm volatile("ld.acquire.gpu.global.u32 %0, [%1];"
                         : "=r"(cur) : "l"(&g_bar4[i].v) : "memory");
        } while (cur < target);
    }
    __syncthreads();
}

extern __shared__ char smem_raw[];

__global__ void __launch_bounds__(T, 2)
fused_att_scores(const float4* __restrict__ X4, const float4* __restrict__ W4,
                 float* __restrict__ out) {
    float4* xbuf = (float4*)smem_raw;                 // 48 KB: this CTA's X rows
    float4* sh   = (float4*)(smem_raw + SH_OFF);      // 6 KB staging
    __shared__ uint64_t mbar_st;
    __shared__ float u0s[3], u1s[3];
    __shared__ int epoch_sh;
    const uint32_t mbar = smem_u32(&mbar_st);
    const int ct  = blockIdx.x;
    const int tid = threadIdx.x;
    const int wid = tid >> 5, lane = tid & 31;

    const int b = ct & 1, chunk = ct >> 1;            // 128 chunks per batch
    const int j0 = ct * 3;                            // this CTA's 3 j-rows
    const char* xsrc = (const char*)(X4 + ((size_t)b * N + chunk * ROWS_PER) * CG);

    // ---- Phase A: epoch, TMA X, W prefetch, colsum -> staged REDG into s. ----
    if (tid == 0) {
        // Counter = k*G exactly at launch start (graph replays serialize), so
        // this pre-arrival read gives the completed-launch count k.
        unsigned v0 = *(volatile unsigned*)&g_bar4[0].v;
        epoch_sh = (int)((v0 / G) & 1u);
        asm volatile("mbarrier.init.shared.b64 [%0], 1;" :: "r"(mbar) : "memory");
        asm volatile("fence.proxy.async.shared::cta;" ::: "memory");
        asm volatile("mbarrier.arrive.expect_tx.shared.b64 _, [%0], %1;"
                     :: "r"(mbar), "r"((uint32_t)XCHUNK_BYTES) : "memory");
        asm volatile(
            "cp.async.bulk.shared::cta.global.mbarrier::complete_tx::bytes "
            "[%0], [%1], %2, [%3];"
            :: "r"(smem_u32(xbuf)), "l"(xsrc), "r"((uint32_t)XCHUNK_BYTES),
               "r"(mbar) : "memory");
    }
    // Prefetch this CTA's 6 W rows into L2 (144 lines of 128B).
    if (tid < 144) {
        const char* wq = (const char*)(W4 + (size_t)j0 * CG);
        const char* wk = (const char*)(W4 + (size_t)(C + j0) * CG);
        const char* p = (tid < 72) ? wq + tid * 128 : wk + (tid - 72) * 128;
        asm volatile("prefetch.global.L2 [%0];" :: "l"(p));
    }
    __syncthreads();
    const int e = epoch_sh;

    // Zero NEXT launch's staged buffers (24 + 48 floats per CTA).
    {
        float* zs = (float*)g_s4[1 - e];              // 6144 floats
        float* zv = (float*)g_v4[1 - e];              // 12288 floats
        if (tid < 24) zs[ct * 24 + tid] = 0.f;
        else if (tid < 72) zv[ct * 48 + (tid - 24)] = 0.f;
    }

    mbar_wait(mbar, 0);
    if (tid < CG) {
        float4 a0 = make_float4(0.f, 0.f, 0.f, 0.f), a1 = a0;
#pragma unroll
        for (int r = 0; r < ROWS_PER; r += 2) {
            a0 = f4add(a0, xbuf[r * CG + tid]);
            a1 = f4add(a1, xbuf[(r + 1) * CG + tid]);
        }
        float4 s = f4add(a0, a1);
        float* dst = &g_s4[e][ct & (SCOPIES - 1)][b][tid * 4];
        atomicAdd(dst + 0, s.x);
        atomicAdd(dst + 1, s.y);
        atomicAdd(dst + 2, s.z);
        atomicAdd(dst + 3, s.w);
    }
    grid_barrier(0);

    // ---- Phase B: sum s copies -> sh; u_j = Wk_j.s; staged REDG of v. ----
    {
        for (int i = tid; i < 2 * CG; i += T) {       // 384 f4 slots
            int bb = (i < CG) ? 0 : 1;
            int idx = (i < CG) ? i : i - CG;
            float4 acc = make_float4(0.f, 0.f, 0.f, 0.f);
#pragma unroll
            for (int c = 0; c < SCOPIES; ++c)
                acc = f4add(acc, *(const float4*)&g_s4[e][c][bb][idx * 4]);
            sh[i] = acc;
        }
        __syncthreads();
        if (wid < 3) {
            const float4* row = W4 + (size_t)(C + j0 + wid) * CG;   // Wk (L2)
            float a0 = 0.f, a1 = 0.f;
#pragma unroll
            for (int k = 0; k < 6; ++k) {
                int c4 = lane + k * 32;
                float4 w  = row[c4];
                float4 v0 = sh[c4];
                float4 v1 = sh[CG + c4];
                a0 += w.x * v0.x + w.y * v0.y + w.z * v0.z + w.w * v0.w;
                a1 += w.x * v1.x + w.y * v1.y + w.z * v1.z + w.w * v1.w;
            }
#pragma unroll
            for (int o = 16; o > 0; o >>= 1) {
                a0 += __shfl_down_sync(0xFFFFFFFFu, a0, o);
                a1 += __shfl_down_sync(0xFFFFFFFFu, a1, o);
            }
            if (lane == 0) { u0s[wid] = a0; u1s[wid] = a1; }
        }
        __syncthreads();
        if (tid < CG) {
            float4 w0 = W4[(size_t)j0 * CG + tid];            // Wq rows (L2)
            float4 w1 = W4[(size_t)(j0 + 1) * CG + tid];
            float4 w2 = W4[(size_t)(j0 + 2) * CG + tid];
            float4 a0 = make_float4(
                w0.x * u0s[0] + w1.x * u0s[1] + w2.x * u0s[2],
                w0.y * u0s[0] + w1.y * u0s[1] + w2.y * u0s[2],
                w0.z * u0s[0] + w1.z * u0s[1] + w2.z * u0s[2],
                w0.w * u0s[0] + w1.w * u0s[1] + w2.w * u0s[2]);
            float4 a1 = make_float4(
                w0.x * u1s[0] + w1.x * u1s[1] + w2.x * u1s[2],
                w0.y * u1s[0] + w1.y * u1s[1] + w2.y * u1s[2],
                w0.z * u1s[0] + w1.z * u1s[1] + w2.z * u1s[2],
                w0.w * u1s[0] + w1.w * u1s[1] + w2.w * u1s[2]);
            int vc = ct & (VCOPIES - 1);
            float* d0 = &g_v4[e][vc][0][tid * 4];
            float* d1 = &g_v4[e][vc][1][tid * 4];
            atomicAdd(d0 + 0, a0.x); atomicAdd(d0 + 1, a0.y);
            atomicAdd(d0 + 2, a0.z); atomicAdd(d0 + 3, a0.w);
            atomicAdd(d1 + 0, a1.x); atomicAdd(d1 + 1, a1.y);
            atomicAdd(d1 + 2, a1.z); atomicAdd(d1 + 3, a1.w);
        }
    }
    grid_barrier(1);

    // ---- Phase C: sum v copies -> sh; scores from retained smem X. ----
    {
        if (tid < CG) {
            float4 acc = make_float4(0.f, 0.f, 0.f, 0.f);
#pragma unroll
            for (int c = 0; c < VCOPIES; ++c)
                acc = f4add(acc, *(const float4*)&g_v4[e][c][b][tid * 4]);
            sh[tid] = acc;
        }
        __syncthreads();
        int nbase = chunk * ROWS_PER + wid * 2;
        float a[2];
#pragma unroll
        for (int r = 0; r < 2; ++r) {
            const float4* x = xbuf + (wid * 2 + r) * CG;
            float acc = 0.f;
#pragma unroll
            for (int k = 0; k < 6; ++k) {
                int c4 = lane + k * 32;
                float4 xv = x[c4];
                float4 vv = sh[c4];
                acc += xv.x * vv.x + xv.y * vv.y + xv.z * vv.z + xv.w * vv.w;
            }
            a[r] = acc;
        }
#pragma unroll
        for (int o = 16; o > 0; o >>= 1) {
#pragma unroll
            for (int r = 0; r < 2; ++r)
                a[r] += __shfl_down_sync(0xFFFFFFFFu, a[r], o);
        }
        if (lane == 0) {
#pragma unroll
            for (int r = 0; r < 2; ++r)
                out[b * N + nbase + r] = 0.125f * a[r];
        }
    }
}

extern "C" void kernel_launch(void* const* d_in, const int* in_sizes, int n_in,
                              void* d_out, int out_size) {
    const float4* X4 = (const float4*)d_in[0];  // [2, 2048, 768] f32
    const float4* W4 = (const float4*)d_in[1];  // [1536, 768] f32
    float* out = (float*)d_out;                 // [2, 2048] f32
    (void)in_sizes; (void)n_in; (void)out_size;

    cudaFuncSetAttribute(fused_att_scores,
                         cudaFuncAttributeMaxDynamicSharedMemorySize, SMEM_BYTES);
    fused_att_scores<<<G, T, SMEM_BYTES>>>(X4, W4, out);
}